// round 4
// baseline (speedup 1.0000x reference)
#include <cuda_runtime.h>
#include <cstdint>
#include <cstddef>

#define BN   16384          // batch
#define TT   10             // timesteps
#define II   184            // input features
#define HH   128            // hidden
#define G4   512            // 4*H (gate width)
#define BT   (BN * TT)      // 163840 rows

// ---------------- scratch (device globals; allocation-free) ----------------
__device__ float g_xp_f[(size_t)BT * G4];   // xproj, forward dir   (335 MB)
__device__ float g_xp_b[(size_t)BT * G4];   // xproj, backward dir  (335 MB)
__device__ float g_out1[(size_t)BT * 256];  // layer-1 output [b][t][2H]
__device__ float g_out2[(size_t)BT * 256];  // layer-2 output [b][t][2H]
__device__ float g_cbuf[2 * (size_t)BN * HH]; // cell state per dir

// ---------------- helpers ----------------
__device__ __forceinline__ float sigm(float x) {
    return 1.0f / (1.0f + __expf(-x));
}

// ============================================================================
// xproj GEMM: C[M,512] = A[M,K] @ W[512,K]^T + (b_ih + b_hh)
// 128x128 block tile, K-tile 8, 256 threads, 8x8 per thread.
// M = BT (multiple of 128), K in {184, 256} (multiple of 8).
// ============================================================================
__global__ __launch_bounds__(256, 2)
void xproj_gemm(const float* __restrict__ A, const float* __restrict__ W,
                const float* __restrict__ bih, const float* __restrict__ bhh,
                float* __restrict__ C, int K)
{
    __shared__ float As[8][128];
    __shared__ float Bs[8][128];

    const int mt = blockIdx.x, nt = blockIdx.y;
    const int tid = threadIdx.x;
    const int tx = tid & 15, ty = tid >> 4;
    const int lrow = tid >> 1;
    const int lk = (tid & 1) * 4;

    const float* Ag = A + (size_t)(mt * 128 + lrow) * K + lk;
    const float* Wg = W + (size_t)(nt * 128 + lrow) * K + lk;

    float acc[8][8];
#pragma unroll
    for (int i = 0; i < 8; i++)
#pragma unroll
        for (int j = 0; j < 8; j++) acc[i][j] = 0.0f;

    for (int k0 = 0; k0 < K; k0 += 8) {
        float4 av = *(const float4*)(Ag + k0);
        float4 bv = *(const float4*)(Wg + k0);
        __syncthreads();
        As[lk + 0][lrow] = av.x; As[lk + 1][lrow] = av.y;
        As[lk + 2][lrow] = av.z; As[lk + 3][lrow] = av.w;
        Bs[lk + 0][lrow] = bv.x; Bs[lk + 1][lrow] = bv.y;
        Bs[lk + 2][lrow] = bv.z; Bs[lk + 3][lrow] = bv.w;
        __syncthreads();
#pragma unroll
        for (int k = 0; k < 8; k++) {
            float a[8], b[8];
            *(float4*)&a[0] = *(const float4*)&As[k][ty * 8];
            *(float4*)&a[4] = *(const float4*)&As[k][ty * 8 + 4];
            *(float4*)&b[0] = *(const float4*)&Bs[k][tx * 8];
            *(float4*)&b[4] = *(const float4*)&Bs[k][tx * 8 + 4];
#pragma unroll
            for (int i = 0; i < 8; i++)
#pragma unroll
                for (int j = 0; j < 8; j++)
                    acc[i][j] += a[i] * b[j];
        }
    }

    float bias[8];
#pragma unroll
    for (int j = 0; j < 8; j++) {
        int n = nt * 128 + tx * 8 + j;
        bias[j] = bih[n] + bhh[n];
    }
#pragma unroll
    for (int i = 0; i < 8; i++) {
        float* Cr = C + (size_t)(mt * 128 + ty * 8 + i) * G4 + nt * 128 + tx * 8;
        float4 v0 = make_float4(acc[i][0] + bias[0], acc[i][1] + bias[1],
                                acc[i][2] + bias[2], acc[i][3] + bias[3]);
        float4 v1 = make_float4(acc[i][4] + bias[4], acc[i][5] + bias[5],
                                acc[i][6] + bias[6], acc[i][7] + bias[7]);
        *(float4*)Cr = v0;
        *(float4*)(Cr + 4) = v1;
    }
}

// ============================================================================
// One LSTM timestep, both directions (grid.y = dir).
// CTA: 64 batch rows x full 512 gate stripe, 512 threads.
// Thread owns 8 rows x {j, j+128, j+256, j+384} for 2 j's -> the full (i,f,g,o)
// quadruple is register-local; cell update needs no cross-thread exchange.
// h_prev is read from the layer-output buffer at t-1 (fwd) / t+1 (bwd).
// step==0: gates = xproj only (h0 = c0 = 0).
// ============================================================================
__global__ __launch_bounds__(512, 1)
void lstm_step(const float* __restrict__ whh_f, const float* __restrict__ whh_b,
               const float* __restrict__ xp_f_, const float* __restrict__ xp_b_,
               float* __restrict__ outbuf, int step)
{
    const int dir = blockIdx.y;
    const int t  = dir ? (TT - 1 - step) : step;
    const int tp = dir ? (t + 1) : (t - 1);
    const float* xp  = dir ? xp_b_ : xp_f_;
    const float* whh = dir ? whh_b : whh_f;
    float* cbuf = g_cbuf + (size_t)dir * BN * HH;

    const int row0 = blockIdx.x * 64;
    const int tid = threadIdx.x;
    const int tr = tid >> 6;   // 0..7 : row group
    const int tc = tid & 63;   // 0..63: j pair (j = tc*2, tc*2+1)

    __shared__ float As[16][64];   // h tile, k-major
    __shared__ float Bs[16][512];  // whh tile, k-major

    float acc[8][8];
#pragma unroll
    for (int r = 0; r < 8; r++)
#pragma unroll
        for (int q = 0; q < 8; q++) acc[r][q] = 0.0f;

    if (step > 0) {
        const int ar  = tid >> 3;  // 0..63 row for A load
        const int akq = tid & 7;   // float2 index along k
        const float* hp = outbuf + ((size_t)(row0 + ar) * TT + tp) * 256
                        + dir * HH + akq * 2;
        for (int k0 = 0; k0 < HH; k0 += 16) {
            float2 av = *(const float2*)(hp + k0);
            float4 bv[4];
#pragma unroll
            for (int u = 0; u < 4; u++) {
                int f = tid + u * 512;
                int n = f >> 2;
                int kq = f & 3;
                bv[u] = *(const float4*)(whh + (size_t)n * HH + k0 + kq * 4);
            }
            __syncthreads();
            As[akq * 2 + 0][ar] = av.x;
            As[akq * 2 + 1][ar] = av.y;
#pragma unroll
            for (int u = 0; u < 4; u++) {
                int f = tid + u * 512;
                int n = f >> 2;
                int kq = f & 3;
                Bs[kq * 4 + 0][n] = bv[u].x; Bs[kq * 4 + 1][n] = bv[u].y;
                Bs[kq * 4 + 2][n] = bv[u].z; Bs[kq * 4 + 3][n] = bv[u].w;
            }
            __syncthreads();
#pragma unroll
            for (int k = 0; k < 16; k++) {
                float a[8];
                *(float4*)&a[0] = *(const float4*)&As[k][tr * 8];
                *(float4*)&a[4] = *(const float4*)&As[k][tr * 8 + 4];
                float2 b0 = *(const float2*)&Bs[k][0 * HH + tc * 2];
                float2 b1 = *(const float2*)&Bs[k][1 * HH + tc * 2];
                float2 b2 = *(const float2*)&Bs[k][2 * HH + tc * 2];
                float2 b3 = *(const float2*)&Bs[k][3 * HH + tc * 2];
#pragma unroll
                for (int r = 0; r < 8; r++) {
                    acc[r][0] += a[r] * b0.x; acc[r][1] += a[r] * b0.y;
                    acc[r][2] += a[r] * b1.x; acc[r][3] += a[r] * b1.y;
                    acc[r][4] += a[r] * b2.x; acc[r][5] += a[r] * b2.y;
                    acc[r][6] += a[r] * b3.x; acc[r][7] += a[r] * b3.y;
                }
            }
        }
    }

    // ---- fused LSTM cell (all in registers) ----
#pragma unroll
    for (int r = 0; r < 8; r++) {
        const int brow = row0 + tr * 8 + r;
        const float* xpr = xp + ((size_t)brow * TT + t) * G4;
        float2 xi = *(const float2*)(xpr + 0 * HH + tc * 2);
        float2 xf = *(const float2*)(xpr + 1 * HH + tc * 2);
        float2 xg = *(const float2*)(xpr + 2 * HH + tc * 2);
        float2 xo = *(const float2*)(xpr + 3 * HH + tc * 2);
        float* crow = cbuf + (size_t)brow * HH + tc * 2;
        float2 cp = (step > 0) ? *(const float2*)crow : make_float2(0.0f, 0.0f);

        float i0 = sigm(acc[r][0] + xi.x), i1 = sigm(acc[r][1] + xi.y);
        float f0 = sigm(acc[r][2] + xf.x), f1 = sigm(acc[r][3] + xf.y);
        float g0 = tanhf(acc[r][4] + xg.x), g1 = tanhf(acc[r][5] + xg.y);
        float o0 = sigm(acc[r][6] + xo.x), o1 = sigm(acc[r][7] + xo.y);

        float2 cn, hn;
        cn.x = f0 * cp.x + i0 * g0;  cn.y = f1 * cp.y + i1 * g1;
        hn.x = o0 * tanhf(cn.x);     hn.y = o1 * tanhf(cn.y);

        *(float2*)crow = cn;
        *(float2*)(outbuf + ((size_t)brow * TT + t) * 256 + dir * HH + tc * 2) = hn;
    }
}

// ============================================================================
// Max-pool (groups of 5 timesteps) + fc1(relu) + fc2, fused.
// v[c*2+p] = max_{u<5} out2[b][5p+u][c];  y[b] = relu(v@W1^T+b1)@W2^T + b2
// fc1 weights cached in smem with row pad 513 (conflict-free stride-513 reads).
// 512 threads, 32 batch rows per block.
// ============================================================================
__global__ void fc_head(const float* __restrict__ out2,
                        const float* __restrict__ w1, const float* __restrict__ b1,
                        const float* __restrict__ w2, const float* __restrict__ b2,
                        float* __restrict__ y)
{
    extern __shared__ float sm[];
    float* wfc = sm;                 // 64 * 513
    float* v   = wfc + 64 * 513;     // 512
    float* red = v + 512;            // 512
    const int tid = threadIdx.x;     // 512 threads

    for (int i = tid; i < 64 * 512; i += 512)
        wfc[(i >> 9) * 513 + (i & 511)] = w1[i];
    __syncthreads();

    const int jj = tid & 63, part = tid >> 6;

    for (int rr = 0; rr < 32; rr++) {
        const int b = blockIdx.x * 32 + rr;
        {   // pooled feature vector: v[tid], tid = c*2+p
            int c = tid >> 1, p = tid & 1;
            const float* p0 = out2 + ((size_t)b * TT + p * 5) * 256 + c;
            float mx = p0[0];
            mx = fmaxf(mx, p0[256]);  mx = fmaxf(mx, p0[512]);
            mx = fmaxf(mx, p0[768]);  mx = fmaxf(mx, p0[1024]);
            v[tid] = mx;
        }
        __syncthreads();

        float s = 0.0f;
        const float* wr = wfc + jj * 513 + part * 64;
        const float* vr = v + part * 64;
#pragma unroll
        for (int i = 0; i < 64; i++) s += wr[i] * vr[i];
        red[tid] = s;
        __syncthreads();

        if (tid < 64) {
            float h = red[tid]       + red[64 + tid]  + red[128 + tid] +
                      red[192 + tid] + red[256 + tid] + red[320 + tid] +
                      red[384 + tid] + red[448 + tid] + b1[tid];
            h = fmaxf(h, 0.0f);
            red[tid] = h * w2[tid];
        }
        __syncthreads();

        if (tid == 0) {
            float s2 = b2[0];
#pragma unroll
            for (int j2 = 0; j2 < 64; j2++) s2 += red[j2];
            y[b] = s2;
        }
        __syncthreads();
    }
}

// ============================================================================
extern "C" void kernel_launch(void* const* d_in, const int* in_sizes, int n_in,
                              void* d_out, int out_size)
{
    (void)in_sizes; (void)n_in; (void)out_size;
    const float* x     = (const float*)d_in[0];
    const float* wih1f = (const float*)d_in[1];
    const float* whh1f = (const float*)d_in[2];
    const float* bih1f = (const float*)d_in[3];
    const float* bhh1f = (const float*)d_in[4];
    const float* wih1b = (const float*)d_in[5];
    const float* whh1b = (const float*)d_in[6];
    const float* bih1b = (const float*)d_in[7];
    const float* bhh1b = (const float*)d_in[8];
    const float* wih2f = (const float*)d_in[9];
    const float* whh2f = (const float*)d_in[10];
    const float* bih2f = (const float*)d_in[11];
    const float* bhh2f = (const float*)d_in[12];
    const float* wih2b = (const float*)d_in[13];
    const float* whh2b = (const float*)d_in[14];
    const float* bih2b = (const float*)d_in[15];
    const float* bhh2b = (const float*)d_in[16];
    const float* fc1w  = (const float*)d_in[17];
    const float* fc1b  = (const float*)d_in[18];
    const float* fc2w  = (const float*)d_in[19];
    const float* fc2b  = (const float*)d_in[20];
    float* y = (float*)d_out;

    float *xpf, *xpb, *o1, *o2;
    cudaGetSymbolAddress((void**)&xpf, g_xp_f);
    cudaGetSymbolAddress((void**)&xpb, g_xp_b);
    cudaGetSymbolAddress((void**)&o1,  g_out1);
    cudaGetSymbolAddress((void**)&o2,  g_out2);

    const dim3 ggrid(BT / 128, 4);     // 1280 x 4 tiles
    const dim3 sgrid(BN / 64, 2);      // 256 M-tiles x 2 directions

    // ---- layer 1 ----
    xproj_gemm<<<ggrid, 256>>>(x, wih1f, bih1f, bhh1f, xpf, II);
    xproj_gemm<<<ggrid, 256>>>(x, wih1b, bih1b, bhh1b, xpb, II);
    for (int s = 0; s < TT; s++)
        lstm_step<<<sgrid, 512>>>(whh1f, whh1b, xpf, xpb, o1, s);

    // ---- layer 2 ----
    xproj_gemm<<<ggrid, 256>>>(o1, wih2f, bih2f, bhh2f, xpf, 256);
    xproj_gemm<<<ggrid, 256>>>(o1, wih2b, bih2b, bhh2b, xpb, 256);
    for (int s = 0; s < TT; s++)
        lstm_step<<<sgrid, 512>>>(whh2f, whh2b, xpf, xpb, o2, s);

    // ---- pool + FC head ----
    cudaFuncSetAttribute(fc_head, cudaFuncAttributeMaxDynamicSharedMemorySize,
                         (64 * 513 + 512 + 512) * (int)sizeof(float));
    fc_head<<<BN / 32, 512, (64 * 513 + 512 + 512) * sizeof(float)>>>(
        o2, fc1w, fc1b, fc2w, fc2b, y);
}

// round 7
// speedup vs baseline: 1.7193x; 1.7193x over previous
#include <cuda_runtime.h>
#include <cstdint>
#include <cstddef>

#define BN   16384          // batch
#define TT   10             // timesteps
#define II   184            // input features
#define HH   128            // hidden
#define G4   512            // 4*H (gate width)
#define BT   (BN * TT)      // 163840 rows

// ---------------- scratch (device globals; allocation-free) ----------------
__device__ float g_xp_f[(size_t)BT * G4];
__device__ float g_xp_b[(size_t)BT * G4];
__device__ float g_out1[(size_t)BT * 256];
__device__ float g_out2[(size_t)BT * 256];
__device__ float g_cbuf[2 * (size_t)BN * HH];

// ---------------- helpers ----------------
__device__ __forceinline__ float sigm(float x) {
    return 1.0f / (1.0f + __expf(-x));
}
__device__ __forceinline__ float tf32r(float x) {
    uint32_t r;
    asm("cvt.rna.tf32.f32 %0, %1;" : "=r"(r) : "f"(x));
    return __uint_as_float(r);
}
__device__ __forceinline__ float4 tf32r4(float4 v) {
    return make_float4(tf32r(v.x), tf32r(v.y), tf32r(v.z), tf32r(v.w));
}
__device__ __forceinline__ void mma8(float c[4], const uint32_t a[4],
                                     const uint32_t b[2]) {
    asm volatile(
        "mma.sync.aligned.m16n8k8.row.col.f32.tf32.tf32.f32 "
        "{%0,%1,%2,%3}, {%4,%5,%6,%7}, {%8,%9}, {%0,%1,%2,%3};"
        : "+f"(c[0]), "+f"(c[1]), "+f"(c[2]), "+f"(c[3])
        : "r"(a[0]), "r"(a[1]), "r"(a[2]), "r"(a[3]), "r"(b[0]), "r"(b[1]));
}
#define FU __float_as_uint

// ============================================================================
// xproj GEMM on tensor cores (mma.sync tf32):
//   C[M,512] = A[M,K] @ W[512,K]^T + (bih + bhh),  K in {184, 256}
// CTA 128x128 tile, 256 threads (8 warps = 4 m-groups x 2 n-groups),
// per warp 2 m16-tiles x 8 n8-tiles. K chunked by 16, double-buffered smem,
// register-staged global loads overlap the MMAs of the previous chunk.
// ============================================================================
#define XSTR 20                        // smem row stride (floats), conflict-safe
#define XBUF (2 * 128 * XSTR)          // floats per stage (A tile + W tile)
#define XP_SMEM (2 * XBUF * 4)         // 40960 bytes

__global__ __launch_bounds__(256, 2)
void xproj_mma(const float* __restrict__ A, const float* __restrict__ W,
               const float* __restrict__ bih, const float* __restrict__ bhh,
               float* __restrict__ C, int K)
{
    extern __shared__ float sx[];
    const int tid = threadIdx.x, l = tid & 31, w = tid >> 5;
    const int gid = l >> 2, tig = l & 3;
    const int mt = blockIdx.x, nt = blockIdx.y;
    const int warpm = w >> 1, warpn = w & 1;
    const int lrow = tid >> 1, lkh = (tid & 1) * 8;   // loader mapping

    const float* Ag = A + (size_t)(mt * 128 + lrow) * K;
    const float* Wg = W + (size_t)(nt * 128 + lrow) * K;
    const int nblk = (K + 15) / 16;

    float4 a0, a1, w0, w1;
    // prologue: global load chunk 0
    {
        const int k0 = lkh;
        a0 = a1 = w0 = w1 = make_float4(0.f, 0.f, 0.f, 0.f);
        if (k0 < K)     a0 = *(const float4*)(Ag + k0);
        if (k0 + 4 < K) a1 = *(const float4*)(Ag + k0 + 4);
        if (k0 < K)     w0 = *(const float4*)(Wg + k0);
        if (k0 + 4 < K) w1 = *(const float4*)(Wg + k0 + 4);
    }
    {   // store chunk 0 -> buffer 0 (tf32-rounded)
        float* As = sx;
        float* Ws = sx + 128 * XSTR;
        *(float4*)(As + lrow * XSTR + lkh)     = tf32r4(a0);
        *(float4*)(As + lrow * XSTR + lkh + 4) = tf32r4(a1);
        *(float4*)(Ws + lrow * XSTR + lkh)     = tf32r4(w0);
        *(float4*)(Ws + lrow * XSTR + lkh + 4) = tf32r4(w1);
    }
    __syncthreads();

    float acc[2][8][4];
#pragma unroll
    for (int m2 = 0; m2 < 2; m2++)
#pragma unroll
        for (int nn = 0; nn < 8; nn++)
#pragma unroll
            for (int r = 0; r < 4; r++) acc[m2][nn][r] = 0.0f;

    for (int c = 0; c < nblk; c++) {
        const float* As = sx + (c & 1) * XBUF;
        const float* Ws = As + 128 * XSTR;
        if (c + 1 < nblk) {               // stage next chunk in registers
            const int k0 = (c + 1) * 16 + lkh;
            a0 = a1 = w0 = w1 = make_float4(0.f, 0.f, 0.f, 0.f);
            if (k0 < K)     a0 = *(const float4*)(Ag + k0);
            if (k0 + 4 < K) a1 = *(const float4*)(Ag + k0 + 4);
            if (k0 < K)     w0 = *(const float4*)(Wg + k0);
            if (k0 + 4 < K) w1 = *(const float4*)(Wg + k0 + 4);
        }
#pragma unroll
        for (int kk = 0; kk < 2; kk++) {
            const int k = kk * 8;
            uint32_t af[2][4];
#pragma unroll
            for (int m2 = 0; m2 < 2; m2++) {
                const int r0 = warpm * 32 + m2 * 16 + gid;
                af[m2][0] = FU(As[r0 * XSTR + k + tig]);
                af[m2][1] = FU(As[(r0 + 8) * XSTR + k + tig]);
                af[m2][2] = FU(As[r0 * XSTR + k + tig + 4]);
                af[m2][3] = FU(As[(r0 + 8) * XSTR + k + tig + 4]);
            }
#pragma unroll
            for (int nn = 0; nn < 8; nn++) {
                const int n0 = warpn * 64 + nn * 8 + gid;
                uint32_t bf[2];
                bf[0] = FU(Ws[n0 * XSTR + k + tig]);
                bf[1] = FU(Ws[n0 * XSTR + k + tig + 4]);
                mma8(acc[0][nn], af[0], bf);
                mma8(acc[1][nn], af[1], bf);
            }
        }
        if (c + 1 < nblk) {               // commit staged chunk to other buffer
            float* As2 = sx + ((c + 1) & 1) * XBUF;
            float* Ws2 = As2 + 128 * XSTR;
            *(float4*)(As2 + lrow * XSTR + lkh)     = tf32r4(a0);
            *(float4*)(As2 + lrow * XSTR + lkh + 4) = tf32r4(a1);
            *(float4*)(Ws2 + lrow * XSTR + lkh)     = tf32r4(w0);
            *(float4*)(Ws2 + lrow * XSTR + lkh + 4) = tf32r4(w1);
        }
        __syncthreads();
    }

    // epilogue: + bias, write C
#pragma unroll
    for (int m2 = 0; m2 < 2; m2++) {
        const int row = mt * 128 + warpm * 32 + m2 * 16 + gid;
#pragma unroll
        for (int nn = 0; nn < 8; nn++) {
            const int col = nt * 128 + warpn * 64 + nn * 8 + tig * 2;
            const float b0v = bih[col] + bhh[col];
            const float b1v = bih[col + 1] + bhh[col + 1];
            *(float2*)(C + (size_t)row * G4 + col) =
                make_float2(acc[m2][nn][0] + b0v, acc[m2][nn][1] + b1v);
            *(float2*)(C + (size_t)(row + 8) * G4 + col) =
                make_float2(acc[m2][nn][2] + b0v, acc[m2][nn][3] + b1v);
        }
    }
}

// ============================================================================
// LSTM timestep on tensor cores. CTA = 64 batch rows x full 512 gate columns,
// 512 threads (16 warps = 4 m-groups x 4 j-groups). Warp: 16 tiles = 4 gates x
// 4 j-subtiles -> (i,f,g,o) quadruple register-local per thread.
// h_prev split hi/lo (2xTF32 MMA) for near-fp32 recurrence; Whh single tf32.
// A (h hi/lo) resident in smem for all K=128; Whh streamed in K-chunks of 16,
// double-buffered with register staging.
// ============================================================================
#define ASTR 132
#define BSTR 20
#define L_APLANE (64 * ASTR)                      // 8448 floats
#define L_BBASE  (2 * L_APLANE)                   // 16896
#define L_BBUF   (512 * BSTR)                     // 10240 floats
#define L_SMEM   ((L_BBASE + 2 * L_BBUF) * 4)     // 149504 bytes

__global__ __launch_bounds__(512, 1)
void lstm_step_tc(const float* __restrict__ whh_f, const float* __restrict__ whh_b,
                  const float* __restrict__ xpf, const float* __restrict__ xpb,
                  float* __restrict__ outbuf, int step)
{
    extern __shared__ float sl[];
    const int dir = blockIdx.y;
    const int t  = dir ? (TT - 1 - step) : step;
    const int tp = dir ? (t + 1) : (t - 1);
    const float* xp  = dir ? xpb : xpf;
    const float* whh = dir ? whh_b : whh_f;
    float* cbuf = g_cbuf + (size_t)dir * BN * HH;
    const int row0 = blockIdx.x * 64;
    const int tid = threadIdx.x, l = tid & 31, w = tid >> 5;
    const int gid = l >> 2, tig = l & 3;
    const int warpm = w >> 2, warpj = w & 3;

    float* Ahi = sl;
    float* Alo = sl + L_APLANE;

    float acc[4][4][4];
#pragma unroll
    for (int g = 0; g < 4; g++)
#pragma unroll
        for (int s = 0; s < 4; s++)
#pragma unroll
            for (int r = 0; r < 4; r++) acc[g][s][r] = 0.0f;

    if (step > 0) {
        // ---- load h_prev tile, split hi/lo into smem ----
#pragma unroll
        for (int i = 0; i < 4; i++) {
            const int f = i * 512 + tid;
            const int r = f >> 5, q = (f & 31) * 4;
            float4 v = *(const float4*)(outbuf +
                        ((size_t)(row0 + r) * TT + tp) * 256 + dir * HH + q);
            float4 hi = tf32r4(v);
            float4 lo = make_float4(tf32r(v.x - hi.x), tf32r(v.y - hi.y),
                                    tf32r(v.z - hi.z), tf32r(v.w - hi.w));
            *(float4*)(Ahi + r * ASTR + q) = hi;
            *(float4*)(Alo + r * ASTR + q) = lo;
        }
        // ---- Whh chunk 0 -> buffer 0 ----
        const int bn = tid >> 2, bq = (tid & 3) * 4;
        float4 bst[4];
#pragma unroll
        for (int i = 0; i < 4; i++)
            bst[i] = *(const float4*)(whh + (size_t)(i * 128 + bn) * HH + bq);
        {
            float* Bs = sl + L_BBASE;
#pragma unroll
            for (int i = 0; i < 4; i++)
                *(float4*)(Bs + (i * 128 + bn) * BSTR + bq) = tf32r4(bst[i]);
        }
        __syncthreads();

        for (int c = 0; c < 8; c++) {
            const float* Bs = sl + L_BBASE + (c & 1) * L_BBUF;
            if (c < 7) {
                const int k0 = (c + 1) * 16;
#pragma unroll
                for (int i = 0; i < 4; i++)
                    bst[i] = *(const float4*)(whh +
                              (size_t)(i * 128 + bn) * HH + k0 + bq);
            }
#pragma unroll
            for (int kk = 0; kk < 2; kk++) {
                const int ka = c * 16 + kk * 8;   // global k for A
                const int kb = kk * 8;            // chunk-local k for B
                uint32_t ah[4], al[4];
                const int r0 = warpm * 16 + gid;
                ah[0] = FU(Ahi[r0 * ASTR + ka + tig]);
                ah[1] = FU(Ahi[(r0 + 8) * ASTR + ka + tig]);
                ah[2] = FU(Ahi[r0 * ASTR + ka + tig + 4]);
                ah[3] = FU(Ahi[(r0 + 8) * ASTR + ka + tig + 4]);
                al[0] = FU(Alo[r0 * ASTR + ka + tig]);
                al[1] = FU(Alo[(r0 + 8) * ASTR + ka + tig]);
                al[2] = FU(Alo[r0 * ASTR + ka + tig + 4]);
                al[3] = FU(Alo[(r0 + 8) * ASTR + ka + tig + 4]);
#pragma unroll
                for (int g = 0; g < 4; g++)
#pragma unroll
                    for (int s = 0; s < 4; s++) {
                        const int n = g * 128 + warpj * 32 + s * 8 + gid;
                        uint32_t bf[2];
                        bf[0] = FU(Bs[n * BSTR + kb + tig]);
                        bf[1] = FU(Bs[n * BSTR + kb + tig + 4]);
                        mma8(acc[g][s], ah, bf);
                        mma8(acc[g][s], al, bf);
                    }
            }
            if (c < 7) {
                float* Bn = sl + L_BBASE + ((c + 1) & 1) * L_BBUF;
#pragma unroll
                for (int i = 0; i < 4; i++)
                    *(float4*)(Bn + (i * 128 + bn) * BSTR + bq) = tf32r4(bst[i]);
            }
            __syncthreads();
        }
    }

    // ---- fused LSTM cell (register-local (i,f,g,o)) ----
#pragma unroll
    for (int half = 0; half < 2; half++) {
        const int brow = row0 + warpm * 16 + gid + half * 8;
        const float* xpr = xp + ((size_t)brow * TT + t) * G4;
        float* crow = cbuf + (size_t)brow * HH;
        float* orow = outbuf + ((size_t)brow * TT + t) * 256 + dir * HH;
#pragma unroll
        for (int s = 0; s < 4; s++) {
            const int jc = warpj * 32 + s * 8 + tig * 2;
            float2 xi = *(const float2*)(xpr + 0 * HH + jc);
            float2 xf = *(const float2*)(xpr + 1 * HH + jc);
            float2 xg = *(const float2*)(xpr + 2 * HH + jc);
            float2 xo = *(const float2*)(xpr + 3 * HH + jc);
            const int p0 = half * 2;
            float i0 = sigm(acc[0][s][p0] + xi.x),  i1 = sigm(acc[0][s][p0 + 1] + xi.y);
            float f0 = sigm(acc[1][s][p0] + xf.x),  f1 = sigm(acc[1][s][p0 + 1] + xf.y);
            float g0 = tanhf(acc[2][s][p0] + xg.x), g1 = tanhf(acc[2][s][p0 + 1] + xg.y);
            float o0 = sigm(acc[3][s][p0] + xo.x),  o1 = sigm(acc[3][s][p0 + 1] + xo.y);
            float2 cp = (step > 0) ? *(const float2*)(crow + jc)
                                   : make_float2(0.f, 0.f);
            float2 cn = make_float2(f0 * cp.x + i0 * g0, f1 * cp.y + i1 * g1);
            float2 hn = make_float2(o0 * tanhf(cn.x), o1 * tanhf(cn.y));
            *(float2*)(crow + jc) = cn;
            *(float2*)(orow + jc) = hn;
        }
    }
}

// ============================================================================
// Max-pool + fc1(relu) + fc2, fused. (unchanged, proven in R3)
// ============================================================================
__global__ void fc_head(const float* __restrict__ out2,
                        const float* __restrict__ w1, const float* __restrict__ b1,
                        const float* __restrict__ w2, const float* __restrict__ b2,
                        float* __restrict__ y)
{
    extern __shared__ float smf[];
    float* wfc = smf;
    float* v   = wfc + 64 * 513;
    float* red = v + 512;
    const int tid = threadIdx.x;

    for (int i = tid; i < 64 * 512; i += 512)
        wfc[(i >> 9) * 513 + (i & 511)] = w1[i];
    __syncthreads();

    const int jj = tid & 63, part = tid >> 6;

    for (int rr = 0; rr < 32; rr++) {
        const int b = blockIdx.x * 32 + rr;
        {
            int c = tid >> 1, p = tid & 1;
            const float* p0 = out2 + ((size_t)b * TT + p * 5) * 256 + c;
            float mx = p0[0];
            mx = fmaxf(mx, p0[256]);  mx = fmaxf(mx, p0[512]);
            mx = fmaxf(mx, p0[768]);  mx = fmaxf(mx, p0[1024]);
            v[tid] = mx;
        }
        __syncthreads();

        float s = 0.0f;
        const float* wr = wfc + jj * 513 + part * 64;
        const float* vr = v + part * 64;
#pragma unroll
        for (int i = 0; i < 64; i++) s += wr[i] * vr[i];
        red[tid] = s;
        __syncthreads();

        if (tid < 64) {
            float h = red[tid]       + red[64 + tid]  + red[128 + tid] +
                      red[192 + tid] + red[256 + tid] + red[320 + tid] +
                      red[384 + tid] + red[448 + tid] + b1[tid];
            h = fmaxf(h, 0.0f);
            red[tid] = h * w2[tid];
        }
        __syncthreads();

        if (tid == 0) {
            float s2 = b2[0];
#pragma unroll
            for (int j2 = 0; j2 < 64; j2++) s2 += red[j2];
            y[b] = s2;
        }
        __syncthreads();
    }
}

// ============================================================================
extern "C" void kernel_launch(void* const* d_in, const int* in_sizes, int n_in,
                              void* d_out, int out_size)
{
    (void)in_sizes; (void)n_in; (void)out_size;
    const float* x     = (const float*)d_in[0];
    const float* wih1f = (const float*)d_in[1];
    const float* whh1f = (const float*)d_in[2];
    const float* bih1f = (const float*)d_in[3];
    const float* bhh1f = (const float*)d_in[4];
    const float* wih1b = (const float*)d_in[5];
    const float* whh1b = (const float*)d_in[6];
    const float* bih1b = (const float*)d_in[7];
    const float* bhh1b = (const float*)d_in[8];
    const float* wih2f = (const float*)d_in[9];
    const float* whh2f = (const float*)d_in[10];
    const float* bih2f = (const float*)d_in[11];
    const float* bhh2f = (const float*)d_in[12];
    const float* wih2b = (const float*)d_in[13];
    const float* whh2b = (const float*)d_in[14];
    const float* bih2b = (const float*)d_in[15];
    const float* bhh2b = (const float*)d_in[16];
    const float* fc1w  = (const float*)d_in[17];
    const float* fc1b  = (const float*)d_in[18];
    const float* fc2w  = (const float*)d_in[19];
    const float* fc2b  = (const float*)d_in[20];
    float* y = (float*)d_out;

    float *xpf, *xpb, *o1, *o2;
    cudaGetSymbolAddress((void**)&xpf, g_xp_f);
    cudaGetSymbolAddress((void**)&xpb, g_xp_b);
    cudaGetSymbolAddress((void**)&o1,  g_out1);
    cudaGetSymbolAddress((void**)&o2,  g_out2);

    cudaFuncSetAttribute(lstm_step_tc, cudaFuncAttributeMaxDynamicSharedMemorySize,
                         (int)L_SMEM);

    const dim3 xgrid(BT / 128, 4);     // 1280 M-tiles x 4 N-tiles
    const dim3 sgrid(BN / 64, 2);      // 256 M-tiles x 2 directions

    // ---- layer 1 ----
    xproj_mma<<<xgrid, 256, XP_SMEM>>>(x, wih1f, bih1f, bhh1f, xpf, II);
    xproj_mma<<<xgrid, 256, XP_SMEM>>>(x, wih1b, bih1b, bhh1b, xpb, II);
    for (int s = 0; s < TT; s++)
        lstm_step_tc<<<sgrid, 512, L_SMEM>>>(whh1f, whh1b, xpf, xpb, o1, s);

    // ---- layer 2 ----
    xproj_mma<<<xgrid, 256, XP_SMEM>>>(o1, wih2f, bih2f, bhh2f, xpf, 256);
    xproj_mma<<<xgrid, 256, XP_SMEM>>>(o1, wih2b, bih2b, bhh2b, xpb, 256);
    for (int s = 0; s < TT; s++)
        lstm_step_tc<<<sgrid, 512, L_SMEM>>>(whh2f, whh2b, xpf, xpb, o2, s);

    // ---- pool + FC head ----
    cudaFuncSetAttribute(fc_head, cudaFuncAttributeMaxDynamicSharedMemorySize,
                         (64 * 513 + 512 + 512) * (int)sizeof(float));
    fc_head<<<BN / 32, 512, (64 * 513 + 512 + 512) * sizeof(float)>>>(
        o2, fc1w, fc1b, fc2w, fc2b, y);
}

// round 8
// speedup vs baseline: 1.7555x; 1.0210x over previous
#include <cuda_runtime.h>
#include <cstdint>
#include <cstddef>

#define BN   16384          // batch
#define TT   10             // timesteps
#define II   184            // input features
#define HH   128            // hidden
#define G4   512            // 4*H (gate width)
#define BT   (BN * TT)      // 163840 rows

// ---------------- scratch (device globals; allocation-free) ----------------
__device__ float g_xp_f[(size_t)BT * G4];
__device__ float g_xp_b[(size_t)BT * G4];
__device__ float g_out1[(size_t)BT * 256];
__device__ float g_out2[(size_t)BT * 256];

// ---------------- helpers ----------------
__device__ __forceinline__ float sigm(float x) {
    return 1.0f / (1.0f + __expf(-x));
}
__device__ __forceinline__ float tf32r(float x) {
    uint32_t r;
    asm("cvt.rna.tf32.f32 %0, %1;" : "=r"(r) : "f"(x));
    return __uint_as_float(r);
}
__device__ __forceinline__ float4 tf32r4(float4 v) {
    return make_float4(tf32r(v.x), tf32r(v.y), tf32r(v.z), tf32r(v.w));
}
__device__ __forceinline__ void mma8(float c[4], const uint32_t a[4],
                                     const uint32_t b[2]) {
    asm volatile(
        "mma.sync.aligned.m16n8k8.row.col.f32.tf32.tf32.f32 "
        "{%0,%1,%2,%3}, {%4,%5,%6,%7}, {%8,%9}, {%0,%1,%2,%3};"
        : "+f"(c[0]), "+f"(c[1]), "+f"(c[2]), "+f"(c[3])
        : "r"(a[0]), "r"(a[1]), "r"(a[2]), "r"(a[3]), "r"(b[0]), "r"(b[1]));
}
#define FU __float_as_uint

__device__ __forceinline__ uint32_t smem_u32(const void* p) {
    uint32_t a;
    asm("{ .reg .u64 t; cvta.to.shared.u64 t, %1; cvt.u32.u64 %0, t; }"
        : "=r"(a) : "l"(p));
    return a;
}
__device__ __forceinline__ void st_peer(uint32_t local_addr, uint32_t peer_rank,
                                        float v) {
    uint32_t pa;
    asm volatile("mapa.shared::cluster.u32 %0, %1, %2;"
                 : "=r"(pa) : "r"(local_addr), "r"(peer_rank));
    asm volatile("st.shared::cluster.f32 [%0], %1;" :: "r"(pa), "f"(v)
                 : "memory");
}

// ============================================================================
// xproj GEMM on tensor cores (mma.sync tf32)   [unchanged from R7, proven]
//   C[M,512] = A[M,K] @ W[512,K]^T + (bih + bhh),  K in {184, 256}
// ============================================================================
#define XSTR 20
#define XBUF (2 * 128 * XSTR)
#define XP_SMEM (2 * XBUF * 4)

__global__ __launch_bounds__(256, 2)
void xproj_mma(const float* __restrict__ A, const float* __restrict__ W,
               const float* __restrict__ bih, const float* __restrict__ bhh,
               float* __restrict__ C, int K)
{
    extern __shared__ float sx[];
    const int tid = threadIdx.x, l = tid & 31, w = tid >> 5;
    const int gid = l >> 2, tig = l & 3;
    const int mt = blockIdx.x, nt = blockIdx.y;
    const int warpm = w >> 1, warpn = w & 1;
    const int lrow = tid >> 1, lkh = (tid & 1) * 8;

    const float* Ag = A + (size_t)(mt * 128 + lrow) * K;
    const float* Wg = W + (size_t)(nt * 128 + lrow) * K;
    const int nblk = (K + 15) / 16;

    float4 a0, a1, w0, w1;
    {
        const int k0 = lkh;
        a0 = a1 = w0 = w1 = make_float4(0.f, 0.f, 0.f, 0.f);
        if (k0 < K)     a0 = *(const float4*)(Ag + k0);
        if (k0 + 4 < K) a1 = *(const float4*)(Ag + k0 + 4);
        if (k0 < K)     w0 = *(const float4*)(Wg + k0);
        if (k0 + 4 < K) w1 = *(const float4*)(Wg + k0 + 4);
    }
    {
        float* As = sx;
        float* Ws = sx + 128 * XSTR;
        *(float4*)(As + lrow * XSTR + lkh)     = tf32r4(a0);
        *(float4*)(As + lrow * XSTR + lkh + 4) = tf32r4(a1);
        *(float4*)(Ws + lrow * XSTR + lkh)     = tf32r4(w0);
        *(float4*)(Ws + lrow * XSTR + lkh + 4) = tf32r4(w1);
    }
    __syncthreads();

    float acc[2][8][4];
#pragma unroll
    for (int m2 = 0; m2 < 2; m2++)
#pragma unroll
        for (int nn = 0; nn < 8; nn++)
#pragma unroll
            for (int r = 0; r < 4; r++) acc[m2][nn][r] = 0.0f;

    for (int c = 0; c < nblk; c++) {
        const float* As = sx + (c & 1) * XBUF;
        const float* Ws = As + 128 * XSTR;
        if (c + 1 < nblk) {
            const int k0 = (c + 1) * 16 + lkh;
            a0 = a1 = w0 = w1 = make_float4(0.f, 0.f, 0.f, 0.f);
            if (k0 < K)     a0 = *(const float4*)(Ag + k0);
            if (k0 + 4 < K) a1 = *(const float4*)(Ag + k0 + 4);
            if (k0 < K)     w0 = *(const float4*)(Wg + k0);
            if (k0 + 4 < K) w1 = *(const float4*)(Wg + k0 + 4);
        }
#pragma unroll
        for (int kk = 0; kk < 2; kk++) {
            const int k = kk * 8;
            uint32_t af[2][4];
#pragma unroll
            for (int m2 = 0; m2 < 2; m2++) {
                const int r0 = warpm * 32 + m2 * 16 + gid;
                af[m2][0] = FU(As[r0 * XSTR + k + tig]);
                af[m2][1] = FU(As[(r0 + 8) * XSTR + k + tig]);
                af[m2][2] = FU(As[r0 * XSTR + k + tig + 4]);
                af[m2][3] = FU(As[(r0 + 8) * XSTR + k + tig + 4]);
            }
#pragma unroll
            for (int nn = 0; nn < 8; nn++) {
                const int n0 = warpn * 64 + nn * 8 + gid;
                uint32_t bf[2];
                bf[0] = FU(Ws[n0 * XSTR + k + tig]);
                bf[1] = FU(Ws[n0 * XSTR + k + tig + 4]);
                mma8(acc[0][nn], af[0], bf);
                mma8(acc[1][nn], af[1], bf);
            }
        }
        if (c + 1 < nblk) {
            float* As2 = sx + ((c + 1) & 1) * XBUF;
            float* Ws2 = As2 + 128 * XSTR;
            *(float4*)(As2 + lrow * XSTR + lkh)     = tf32r4(a0);
            *(float4*)(As2 + lrow * XSTR + lkh + 4) = tf32r4(a1);
            *(float4*)(Ws2 + lrow * XSTR + lkh)     = tf32r4(w0);
            *(float4*)(Ws2 + lrow * XSTR + lkh + 4) = tf32r4(w1);
        }
        __syncthreads();
    }

#pragma unroll
    for (int m2 = 0; m2 < 2; m2++) {
        const int row = mt * 128 + warpm * 32 + m2 * 16 + gid;
#pragma unroll
        for (int nn = 0; nn < 8; nn++) {
            const int col = nt * 128 + warpn * 64 + nn * 8 + tig * 2;
            const float b0v = bih[col] + bhh[col];
            const float b1v = bih[col + 1] + bhh[col + 1];
            *(float2*)(C + (size_t)row * G4 + col) =
                make_float2(acc[m2][nn][0] + b0v, acc[m2][nn][1] + b1v);
            *(float2*)(C + (size_t)(row + 8) * G4 + col) =
                make_float2(acc[m2][nn][2] + b0v, acc[m2][nn][3] + b1v);
        }
    }
}

// ============================================================================
// Persistent LSTM layer kernel: one launch runs all 10 timesteps.
// Cluster of 2 CTAs shares 64 batch rows; CTA q computes ALL 4 gates for
// hidden columns [q*64, q*64+64) -> Whh slice (256x128) stays RESIDENT in
// smem for the whole layer. h lives in smem (A operand), exchanged across the
// cluster via DSMEM stores each step; c lives in registers.
//
// 512 threads = 16 warps: warpm in 0..1 (32 rows), warpj in 0..7 (8 j-cols).
// Per warp per k-step: 2 m16-tiles x 4 gate-tiles = 8 mma8, 8 LDS.64.
// Smem float2 layouts pack k-pairs (k, k+4): p = (k>>3)*4 + (k&3),
// slot = (k>>2)&1, so fragments load as single float2.
// ============================================================================
#define A_F2S  65                              // A row stride in float2
#define B_F2S  65                              // B row stride in float2
#define A_FLOATS (64 * A_F2S * 2)              // 8320
#define B_FLOATS (256 * B_F2S * 2)             // 33280
#define L_SMEM  ((A_FLOATS + B_FLOATS) * 4)    // 166400 bytes

__global__ __launch_bounds__(512, 1) __cluster_dims__(2, 1, 1)
void lstm_layer(const float* __restrict__ whh_f, const float* __restrict__ whh_b,
                const float* __restrict__ xpf, const float* __restrict__ xpb,
                float* __restrict__ outbuf)
{
    extern __shared__ float sl[];
    float*  Afl = sl;
    float2* A2  = (float2*)sl;
    float*  Bfl = sl + A_FLOATS;
    float2* B2  = (float2*)Bfl;

    uint32_t q;
    asm("mov.u32 %0, %%cluster_ctarank;" : "=r"(q));
    const uint32_t peer = q ^ 1u;
    const int rowblk = blockIdx.x >> 1;
    const int dir = blockIdx.y;
    const int row0 = rowblk * 64;
    const float* xp  = dir ? xpb : xpf;
    const float* whh = dir ? whh_b : whh_f;

    const int tid = threadIdx.x, l = tid & 31, w = tid >> 5;
    const int gid = l >> 2, tig = l & 3;
    const int warpm = w >> 3;            // 0..1  (32 rows each)
    const int warpj = w & 7;             // 0..7  (8 j-cols each)

    // ---- load resident Whh slice once: rows n_g = g*128 + q*64 + jl ----
    {
        const int nb = tid >> 1;                 // 0..255 local row
        const int g = nb >> 6, jl = nb & 63;
        const int kh = (tid & 1) * 64;
        const float* src = whh + (size_t)(g * 128 + (int)q * 64 + jl) * HH + kh;
#pragma unroll
        for (int i = 0; i < 16; i++) {
            float4 v = *(const float4*)(src + i * 4);
            const float vv[4] = {tf32r(v.x), tf32r(v.y), tf32r(v.z), tf32r(v.w)};
#pragma unroll
            for (int j = 0; j < 4; j++) {
                const int k = kh + i * 4 + j;
                const int p = (k >> 3) * 4 + (k & 3);
                const int s = (k >> 2) & 1;
                Bfl[nb * (B_F2S * 2) + p * 2 + s] = vv[j];
            }
        }
    }

    // per-thread fixed coordinates
    const int jl2 = warpj * 8 + tig * 2;          // local j of cols (jl2, jl2+1)
    const int jg  = (int)q * 64 + jl2;            // global hidden col
    const int pA  = (jg >> 3) * 4 + (jg & 3);     // A pair index for h writes
    const int sA  = (jg >> 2) & 1;                // slot (same for jg and jg+1)

    float2 cc[4];                                 // cell state (4 rows x 2 cols)

    for (int ti = 0; ti < TT; ti++) {
        const int t = dir ? (TT - 1 - ti) : ti;

        float acc[2][4][4];
#pragma unroll
        for (int m2 = 0; m2 < 2; m2++)
#pragma unroll
            for (int g = 0; g < 4; g++)
#pragma unroll
                for (int r = 0; r < 4; r++) acc[m2][g][r] = 0.0f;

        // prefetch xp for this step (overlaps MMA loop via scoreboard)
        float2 xr[4][4];
#pragma unroll
        for (int r = 0; r < 4; r++) {
            const int brow = row0 + warpm * 32 + (r >> 1) * 16 + (r & 1) * 8 + gid;
            const float* xpr = xp + ((size_t)brow * TT + t) * G4 + jg;
#pragma unroll
            for (int g = 0; g < 4; g++)
                xr[r][g] = *(const float2*)(xpr + g * HH);
        }

        if (ti > 0) {
            const int r0 = warpm * 32 + gid;
#pragma unroll
            for (int kk = 0; kk < 16; kk++) {
                const int p = kk * 4 + tig;
                float2 fa0 = A2[(r0)      * A_F2S + p];
                float2 fa1 = A2[(r0 + 8)  * A_F2S + p];
                float2 fa2 = A2[(r0 + 16) * A_F2S + p];
                float2 fa3 = A2[(r0 + 24) * A_F2S + p];
                const uint32_t a0[4] = {FU(fa0.x), FU(fa1.x), FU(fa0.y), FU(fa1.y)};
                const uint32_t a1[4] = {FU(fa2.x), FU(fa3.x), FU(fa2.y), FU(fa3.y)};
#pragma unroll
                for (int g = 0; g < 4; g++) {
                    const int nb = g * 64 + warpj * 8 + gid;
                    float2 fw = B2[nb * B_F2S + p];
                    const uint32_t bf[2] = {FU(fw.x), FU(fw.y)};
                    mma8(acc[0][g], a0, bf);
                    mma8(acc[1][g], a1, bf);
                }
            }
        }
        __syncthreads();          // all A reads done before cell overwrites A

        // ---- fused LSTM cell; write h to outbuf + both CTAs' A planes ----
#pragma unroll
        for (int r = 0; r < 4; r++) {
            const int m2 = r >> 1, rh = r & 1;
            const int lr = warpm * 32 + m2 * 16 + rh * 8 + gid;
            const int brow = row0 + lr;
            const int e = rh * 2;

            float i0 = sigm(acc[m2][0][e]     + xr[r][0].x);
            float i1 = sigm(acc[m2][0][e + 1] + xr[r][0].y);
            float f0 = sigm(acc[m2][1][e]     + xr[r][1].x);
            float f1 = sigm(acc[m2][1][e + 1] + xr[r][1].y);
            float g0 = tanhf(acc[m2][2][e]     + xr[r][2].x);
            float g1 = tanhf(acc[m2][2][e + 1] + xr[r][2].y);
            float o0 = sigm(acc[m2][3][e]     + xr[r][3].x);
            float o1 = sigm(acc[m2][3][e + 1] + xr[r][3].y);

            float2 cp = (ti > 0) ? cc[r] : make_float2(0.f, 0.f);
            float2 cn = make_float2(f0 * cp.x + i0 * g0, f1 * cp.y + i1 * g1);
            float2 hn = make_float2(o0 * tanhf(cn.x), o1 * tanhf(cn.y));
            cc[r] = cn;

            *(float2*)(outbuf + ((size_t)brow * TT + t) * 256 + dir * HH + jg) = hn;

            const float h0 = tf32r(hn.x), h1 = tf32r(hn.y);
            float* dst = &Afl[lr * (A_F2S * 2) + pA * 2 + sA];
            dst[0] = h0;
            dst[2] = h1;                         // pA+1, same slot
            const uint32_t da = smem_u32(dst);
            st_peer(da,     peer, h0);
            st_peer(da + 8, peer, h1);
        }
        __syncthreads();
        asm volatile("barrier.cluster.arrive.aligned;" ::: "memory");
        asm volatile("barrier.cluster.wait.aligned;"   ::: "memory");
    }
}

// ============================================================================
// Max-pool + fc1(relu) + fc2, fused. (unchanged, proven)
// ============================================================================
__global__ void fc_head(const float* __restrict__ out2,
                        const float* __restrict__ w1, const float* __restrict__ b1,
                        const float* __restrict__ w2, const float* __restrict__ b2,
                        float* __restrict__ y)
{
    extern __shared__ float smf[];
    float* wfc = smf;
    float* v   = wfc + 64 * 513;
    float* red = v + 512;
    const int tid = threadIdx.x;

    for (int i = tid; i < 64 * 512; i += 512)
        wfc[(i >> 9) * 513 + (i & 511)] = w1[i];
    __syncthreads();

    const int jj = tid & 63, part = tid >> 6;

    for (int rr = 0; rr < 32; rr++) {
        const int b = blockIdx.x * 32 + rr;
        {
            int c = tid >> 1, p = tid & 1;
            const float* p0 = out2 + ((size_t)b * TT + p * 5) * 256 + c;
            float mx = p0[0];
            mx = fmaxf(mx, p0[256]);  mx = fmaxf(mx, p0[512]);
            mx = fmaxf(mx, p0[768]);  mx = fmaxf(mx, p0[1024]);
            v[tid] = mx;
        }
        __syncthreads();

        float s = 0.0f;
        const float* wr = wfc + jj * 513 + part * 64;
        const float* vr = v + part * 64;
#pragma unroll
        for (int i = 0; i < 64; i++) s += wr[i] * vr[i];
        red[tid] = s;
        __syncthreads();

        if (tid < 64) {
            float h = red[tid]       + red[64 + tid]  + red[128 + tid] +
                      red[192 + tid] + red[256 + tid] + red[320 + tid] +
                      red[384 + tid] + red[448 + tid] + b1[tid];
            h = fmaxf(h, 0.0f);
            red[tid] = h * w2[tid];
        }
        __syncthreads();

        if (tid == 0) {
            float s2 = b2[0];
#pragma unroll
            for (int j2 = 0; j2 < 64; j2++) s2 += red[j2];
            y[b] = s2;
        }
        __syncthreads();
    }
}

// ============================================================================
extern "C" void kernel_launch(void* const* d_in, const int* in_sizes, int n_in,
                              void* d_out, int out_size)
{
    (void)in_sizes; (void)n_in; (void)out_size;
    const float* x     = (const float*)d_in[0];
    const float* wih1f = (const float*)d_in[1];
    const float* whh1f = (const float*)d_in[2];
    const float* bih1f = (const float*)d_in[3];
    const float* bhh1f = (const float*)d_in[4];
    const float* wih1b = (const float*)d_in[5];
    const float* whh1b = (const float*)d_in[6];
    const float* bih1b = (const float*)d_in[7];
    const float* bhh1b = (const float*)d_in[8];
    const float* wih2f = (const float*)d_in[9];
    const float* whh2f = (const float*)d_in[10];
    const float* bih2f = (const float*)d_in[11];
    const float* bhh2f = (const float*)d_in[12];
    const float* wih2b = (const float*)d_in[13];
    const float* whh2b = (const float*)d_in[14];
    const float* bih2b = (const float*)d_in[15];
    const float* bhh2b = (const float*)d_in[16];
    const float* fc1w  = (const float*)d_in[17];
    const float* fc1b  = (const float*)d_in[18];
    const float* fc2w  = (const float*)d_in[19];
    const float* fc2b  = (const float*)d_in[20];
    float* y = (float*)d_out;

    float *xpf, *xpb, *o1, *o2;
    cudaGetSymbolAddress((void**)&xpf, g_xp_f);
    cudaGetSymbolAddress((void**)&xpb, g_xp_b);
    cudaGetSymbolAddress((void**)&o1,  g_out1);
    cudaGetSymbolAddress((void**)&o2,  g_out2);

    cudaFuncSetAttribute(lstm_layer, cudaFuncAttributeMaxDynamicSharedMemorySize,
                         (int)L_SMEM);

    const dim3 xgrid(BT / 128, 4);     // xproj: 1280 M-tiles x 4 N-tiles
    const dim3 lgrid(2 * (BN / 64), 2);// lstm: (2 cluster CTAs x 256 blks) x 2 dir

    // ---- layer 1 ----
    xproj_mma<<<xgrid, 256, XP_SMEM>>>(x, wih1f, bih1f, bhh1f, xpf, II);
    xproj_mma<<<xgrid, 256, XP_SMEM>>>(x, wih1b, bih1b, bhh1b, xpb, II);
    lstm_layer<<<lgrid, 512, L_SMEM>>>(whh1f, whh1b, xpf, xpb, o1);

    // ---- layer 2 ----
    xproj_mma<<<xgrid, 256, XP_SMEM>>>(o1, wih2f, bih2f, bhh2f, xpf, 256);
    xproj_mma<<<xgrid, 256, XP_SMEM>>>(o1, wih2b, bih2b, bhh2b, xpb, 256);
    lstm_layer<<<lgrid, 512, L_SMEM>>>(whh2f, whh2b, xpf, xpb, o2);

    // ---- pool + FC head ----
    cudaFuncSetAttribute(fc_head, cudaFuncAttributeMaxDynamicSharedMemorySize,
                         (64 * 513 + 512 + 512) * (int)sizeof(float));
    fc_head<<<BN / 32, 512, (64 * 513 + 512 + 512) * sizeof(float)>>>(
        o2, fc1w, fc1b, fc2w, fc2b, y);
}

// round 10
// speedup vs baseline: 2.2454x; 1.2791x over previous
#include <cuda_runtime.h>
#include <cstdint>
#include <cstddef>

#define BN   16384          // batch
#define TT   10             // timesteps
#define II   184            // input features
#define HH   128            // hidden
#define G4   512            // 4*H (gate width)
#define BT   (BN * TT)      // 163840 rows

// ---------------- scratch (device globals; allocation-free) ----------------
__device__ float g_xp_f[(size_t)BT * G4];
__device__ float g_xp_b[(size_t)BT * G4];
__device__ float g_out1[(size_t)BT * 256];
__device__ float g_out2[(size_t)BT * 256];

// ---------------- helpers ----------------
__device__ __forceinline__ float sigm(float x) {
    return 1.0f / (1.0f + __expf(-x));
}
__device__ __forceinline__ float tf32r(float x) {
    uint32_t r;
    asm("cvt.rna.tf32.f32 %0, %1;" : "=r"(r) : "f"(x));
    return __uint_as_float(r);
}
__device__ __forceinline__ void mma8(float c[4], const uint32_t a[4],
                                     const uint32_t b[2]) {
    asm volatile(
        "mma.sync.aligned.m16n8k8.row.col.f32.tf32.tf32.f32 "
        "{%0,%1,%2,%3}, {%4,%5,%6,%7}, {%8,%9}, {%0,%1,%2,%3};"
        : "+f"(c[0]), "+f"(c[1]), "+f"(c[2]), "+f"(c[3])
        : "r"(a[0]), "r"(a[1]), "r"(a[2]), "r"(a[3]), "r"(b[0]), "r"(b[1]));
}
#define FU __float_as_uint

__device__ __forceinline__ uint32_t smem_u32(const void* p) {
    uint32_t a;
    asm("{ .reg .u64 t; cvta.to.shared.u64 t, %1; cvt.u32.u64 %0, t; }"
        : "=r"(a) : "l"(p));
    return a;
}
__device__ __forceinline__ void st_peer(uint32_t local_addr, uint32_t peer_rank,
                                        float v) {
    uint32_t pa;
    asm volatile("mapa.shared::cluster.u32 %0, %1, %2;"
                 : "=r"(pa) : "r"(local_addr), "r"(peer_rank));
    asm volatile("st.shared::cluster.f32 [%0], %1;" :: "r"(pa), "f"(v)
                 : "memory");
}

// ============================================================================
// xproj GEMM on tensor cores (mma.sync tf32):
//   C[M,512] = A[M,K] @ W[512,K]^T + (bih + bhh),  K in {184, 256}
// CTA 128x128, 256 threads (8 warps = 4 m x 2 n), warp tile 32m x 64n.
// K chunked by 16, double-buffered. Smem stores k-pairs (k, k+4) as float2,
// row stride 12 float2 (== 12 mod 16 -> conflict-free LDS.64 fragments).
// Grid is (nt, mt) so a wave shares each A tile across all 4 nt in L2.
// ============================================================================
#define XP2S  12                        // row stride in float2
#define XBUF2 (2 * 128 * XP2S)          // float2 per stage (A tile + W tile)
#define XP_SMEM (2 * XBUF2 * 8)         // 49152 bytes

__global__ __launch_bounds__(256, 2)
void xproj_mma(const float* __restrict__ A, const float* __restrict__ W,
               const float* __restrict__ bih, const float* __restrict__ bhh,
               float* __restrict__ C, int K)
{
    extern __shared__ float2 sx2[];
    const int tid = threadIdx.x, l = tid & 31, w = tid >> 5;
    const int gid = l >> 2, tig = l & 3;
    const int nt = blockIdx.x, mt = blockIdx.y;
    const int warpm = w >> 1, warpn = w & 1;
    const int lrow = tid >> 1, lkh = (tid & 1) * 8;
    const int lpb = (lkh >> 3) * 4;                 // pair base 0 or 4

    const float* Ag = A + (size_t)(mt * 128 + lrow) * K;
    const float* Wg = W + (size_t)(nt * 128 + lrow) * K;
    const int nblk = (K + 15) / 16;

    float4 a0, a1, w0, w1;
    {
        const int k0 = lkh;
        a0 = a1 = w0 = w1 = make_float4(0.f, 0.f, 0.f, 0.f);
        if (k0 < K)     a0 = *(const float4*)(Ag + k0);
        if (k0 + 4 < K) a1 = *(const float4*)(Ag + k0 + 4);
        if (k0 < K)     w0 = *(const float4*)(Wg + k0);
        if (k0 + 4 < K) w1 = *(const float4*)(Wg + k0 + 4);
    }
    {   // pack pairs {a0.j, a1.j} at pair index lpb+j
        float2* As = sx2;
        float2* Ws = sx2 + 128 * XP2S;
        As[lrow * XP2S + lpb + 0] = make_float2(tf32r(a0.x), tf32r(a1.x));
        As[lrow * XP2S + lpb + 1] = make_float2(tf32r(a0.y), tf32r(a1.y));
        As[lrow * XP2S + lpb + 2] = make_float2(tf32r(a0.z), tf32r(a1.z));
        As[lrow * XP2S + lpb + 3] = make_float2(tf32r(a0.w), tf32r(a1.w));
        Ws[lrow * XP2S + lpb + 0] = make_float2(tf32r(w0.x), tf32r(w1.x));
        Ws[lrow * XP2S + lpb + 1] = make_float2(tf32r(w0.y), tf32r(w1.y));
        Ws[lrow * XP2S + lpb + 2] = make_float2(tf32r(w0.z), tf32r(w1.z));
        Ws[lrow * XP2S + lpb + 3] = make_float2(tf32r(w0.w), tf32r(w1.w));
    }
    __syncthreads();

    float acc[2][8][4];
#pragma unroll
    for (int m2 = 0; m2 < 2; m2++)
#pragma unroll
        for (int nn = 0; nn < 8; nn++)
#pragma unroll
            for (int r = 0; r < 4; r++) acc[m2][nn][r] = 0.0f;

    for (int c = 0; c < nblk; c++) {
        const float2* As = sx2 + (c & 1) * XBUF2;
        const float2* Ws = As + 128 * XP2S;
        if (c + 1 < nblk) {
            const int k0 = (c + 1) * 16 + lkh;
            a0 = a1 = w0 = w1 = make_float4(0.f, 0.f, 0.f, 0.f);
            if (k0 < K)     a0 = *(const float4*)(Ag + k0);
            if (k0 + 4 < K) a1 = *(const float4*)(Ag + k0 + 4);
            if (k0 < K)     w0 = *(const float4*)(Wg + k0);
            if (k0 + 4 < K) w1 = *(const float4*)(Wg + k0 + 4);
        }
#pragma unroll
        for (int kk = 0; kk < 2; kk++) {
            const int p = kk * 4 + tig;
            uint32_t af[2][4];
#pragma unroll
            for (int m2 = 0; m2 < 2; m2++) {
                const int r0 = warpm * 32 + m2 * 16 + gid;
                float2 f0 = As[r0 * XP2S + p];
                float2 f1 = As[(r0 + 8) * XP2S + p];
                af[m2][0] = FU(f0.x); af[m2][1] = FU(f1.x);
                af[m2][2] = FU(f0.y); af[m2][3] = FU(f1.y);
            }
#pragma unroll
            for (int nn = 0; nn < 8; nn++) {
                const int n0 = warpn * 64 + nn * 8 + gid;
                float2 fw = Ws[n0 * XP2S + p];
                const uint32_t bf[2] = {FU(fw.x), FU(fw.y)};
                mma8(acc[0][nn], af[0], bf);
                mma8(acc[1][nn], af[1], bf);
            }
        }
        if (c + 1 < nblk) {
            float2* As2 = sx2 + ((c + 1) & 1) * XBUF2;
            float2* Ws2 = As2 + 128 * XP2S;
            As2[lrow * XP2S + lpb + 0] = make_float2(tf32r(a0.x), tf32r(a1.x));
            As2[lrow * XP2S + lpb + 1] = make_float2(tf32r(a0.y), tf32r(a1.y));
            As2[lrow * XP2S + lpb + 2] = make_float2(tf32r(a0.z), tf32r(a1.z));
            As2[lrow * XP2S + lpb + 3] = make_float2(tf32r(a0.w), tf32r(a1.w));
            Ws2[lrow * XP2S + lpb + 0] = make_float2(tf32r(w0.x), tf32r(w1.x));
            Ws2[lrow * XP2S + lpb + 1] = make_float2(tf32r(w0.y), tf32r(w1.y));
            Ws2[lrow * XP2S + lpb + 2] = make_float2(tf32r(w0.z), tf32r(w1.z));
            Ws2[lrow * XP2S + lpb + 3] = make_float2(tf32r(w0.w), tf32r(w1.w));
        }
        __syncthreads();
    }

#pragma unroll
    for (int m2 = 0; m2 < 2; m2++) {
        const int row = mt * 128 + warpm * 32 + m2 * 16 + gid;
#pragma unroll
        for (int nn = 0; nn < 8; nn++) {
            const int col = nt * 128 + warpn * 64 + nn * 8 + tig * 2;
            const float b0v = bih[col] + bhh[col];
            const float b1v = bih[col + 1] + bhh[col + 1];
            *(float2*)(C + (size_t)row * G4 + col) =
                make_float2(acc[m2][nn][0] + b0v, acc[m2][nn][1] + b1v);
            *(float2*)(C + (size_t)(row + 8) * G4 + col) =
                make_float2(acc[m2][nn][2] + b0v, acc[m2][nn][3] + b1v);
        }
    }
}

// ============================================================================
// Persistent LSTM layer kernel (cluster-2, resident Whh slice, h in smem,
// c in registers). Stride 68 float2 (== 4 mod 16): fragment LDS.64
// bank-pair = (4*gid + tig) mod 16 -> conflict-free per 16-lane phase.
// ============================================================================
#define A_F2S  68                              // A row stride in float2
#define B_F2S  68                              // B row stride in float2
#define A_FLOATS (64 * A_F2S * 2)              // 8704
#define B_FLOATS (256 * B_F2S * 2)             // 34816
#define L_SMEM  ((A_FLOATS + B_FLOATS) * 4)    // 174080 bytes

__global__ __launch_bounds__(512, 1) __cluster_dims__(2, 1, 1)
void lstm_layer(const float* __restrict__ whh_f, const float* __restrict__ whh_b,
                const float* __restrict__ xpf, const float* __restrict__ xpb,
                float* __restrict__ outbuf)
{
    extern __shared__ float sl[];
    float*  Afl = sl;
    float2* A2  = (float2*)sl;
    float*  Bfl = sl + A_FLOATS;
    float2* B2  = (float2*)Bfl;

    uint32_t q;
    asm("mov.u32 %0, %%cluster_ctarank;" : "=r"(q));
    const uint32_t peer = q ^ 1u;
    const int rowblk = blockIdx.x >> 1;
    const int dir = blockIdx.y;
    const int row0 = rowblk * 64;
    const float* xp  = dir ? xpb : xpf;
    const float* whh = dir ? whh_b : whh_f;

    const int tid = threadIdx.x, l = tid & 31, w = tid >> 5;
    const int gid = l >> 2, tig = l & 3;
    const int warpm = w >> 3;            // 0..1  (32 rows each)
    const int warpj = w & 7;             // 0..7  (8 j-cols each)

    // ---- load resident Whh slice once: rows n_g = g*128 + q*64 + jl ----
    {
        const int nb = tid >> 1;                 // 0..255 local row
        const int g = nb >> 6, jl = nb & 63;
        const int kh = (tid & 1) * 64;
        const float* src = whh + (size_t)(g * 128 + (int)q * 64 + jl) * HH + kh;
#pragma unroll
        for (int i = 0; i < 16; i++) {
            float4 v = *(const float4*)(src + i * 4);
            const float vv[4] = {tf32r(v.x), tf32r(v.y), tf32r(v.z), tf32r(v.w)};
#pragma unroll
            for (int j = 0; j < 4; j++) {
                const int k = kh + i * 4 + j;
                const int p = (k >> 3) * 4 + (k & 3);
                const int s = (k >> 2) & 1;
                Bfl[nb * (B_F2S * 2) + p * 2 + s] = vv[j];
            }
        }
    }

    // per-thread fixed coordinates
    const int jl2 = warpj * 8 + tig * 2;          // local j of cols (jl2, jl2+1)
    const int jg  = (int)q * 64 + jl2;            // global hidden col
    const int pA  = (jg >> 3) * 4 + (jg & 3);     // A pair index for h writes
    const int sA  = (jg >> 2) & 1;                // slot (same for jg and jg+1)

    float2 cc[4];                                 // cell state (4 rows x 2 cols)

    for (int ti = 0; ti < TT; ti++) {
        const int t = dir ? (TT - 1 - ti) : ti;

        float acc[2][4][4];
#pragma unroll
        for (int m2 = 0; m2 < 2; m2++)
#pragma unroll
            for (int g = 0; g < 4; g++)
#pragma unroll
                for (int r = 0; r < 4; r++) acc[m2][g][r] = 0.0f;

        // prefetch xp for this step (overlaps MMA loop via scoreboard)
        float2 xr[4][4];
#pragma unroll
        for (int r = 0; r < 4; r++) {
            const int brow = row0 + warpm * 32 + (r >> 1) * 16 + (r & 1) * 8 + gid;
            const float* xpr = xp + ((size_t)brow * TT + t) * G4 + jg;
#pragma unroll
            for (int g = 0; g < 4; g++)
                xr[r][g] = *(const float2*)(xpr + g * HH);
        }

        if (ti > 0) {
            const int r0 = warpm * 32 + gid;
#pragma unroll
            for (int kk = 0; kk < 16; kk++) {
                const int p = kk * 4 + tig;
                float2 fa0 = A2[(r0)      * A_F2S + p];
                float2 fa1 = A2[(r0 + 8)  * A_F2S + p];
                float2 fa2 = A2[(r0 + 16) * A_F2S + p];
                float2 fa3 = A2[(r0 + 24) * A_F2S + p];
                const uint32_t a0[4] = {FU(fa0.x), FU(fa1.x), FU(fa0.y), FU(fa1.y)};
                const uint32_t a1[4] = {FU(fa2.x), FU(fa3.x), FU(fa2.y), FU(fa3.y)};
#pragma unroll
                for (int g = 0; g < 4; g++) {
                    const int nb = g * 64 + warpj * 8 + gid;
                    float2 fw = B2[nb * B_F2S + p];
                    const uint32_t bf[2] = {FU(fw.x), FU(fw.y)};
                    mma8(acc[0][g], a0, bf);
                    mma8(acc[1][g], a1, bf);
                }
            }
        }
        __syncthreads();          // all A reads done before cell overwrites A

        // ---- fused LSTM cell; write h to outbuf + both CTAs' A planes ----
#pragma unroll
        for (int r = 0; r < 4; r++) {
            const int m2 = r >> 1, rh = r & 1;
            const int lr = warpm * 32 + m2 * 16 + rh * 8 + gid;
            const int brow = row0 + lr;
            const int e = rh * 2;

            float i0 = sigm(acc[m2][0][e]     + xr[r][0].x);
            float i1 = sigm(acc[m2][0][e + 1] + xr[r][0].y);
            float f0 = sigm(acc[m2][1][e]     + xr[r][1].x);
            float f1 = sigm(acc[m2][1][e + 1] + xr[r][1].y);
            float g0 = tanhf(acc[m2][2][e]     + xr[r][2].x);
            float g1 = tanhf(acc[m2][2][e + 1] + xr[r][2].y);
            float o0 = sigm(acc[m2][3][e]     + xr[r][3].x);
            float o1 = sigm(acc[m2][3][e + 1] + xr[r][3].y);

            float2 cp = (ti > 0) ? cc[r] : make_float2(0.f, 0.f);
            float2 cn = make_float2(f0 * cp.x + i0 * g0, f1 * cp.y + i1 * g1);
            float2 hn = make_float2(o0 * tanhf(cn.x), o1 * tanhf(cn.y));
            cc[r] = cn;

            *(float2*)(outbuf + ((size_t)brow * TT + t) * 256 + dir * HH + jg) = hn;

            const float h0 = tf32r(hn.x), h1 = tf32r(hn.y);
            float* dst = &Afl[lr * (A_F2S * 2) + pA * 2 + sA];
            dst[0] = h0;
            dst[2] = h1;                         // pA+1, same slot
            const uint32_t da = smem_u32(dst);
            st_peer(da,     peer, h0);
            st_peer(da + 8, peer, h1);
        }
        __syncthreads();
        asm volatile("barrier.cluster.arrive.aligned;" ::: "memory");
        asm volatile("barrier.cluster.wait.aligned;"   ::: "memory");
    }
}

// ============================================================================
// Max-pool + fc1(relu) + fc2, fused. (unchanged, proven)
// ============================================================================
__global__ void fc_head(const float* __restrict__ out2,
                        const float* __restrict__ w1, const float* __restrict__ b1,
                        const float* __restrict__ w2, const float* __restrict__ b2,
                        float* __restrict__ y)
{
    extern __shared__ float smf[];
    float* wfc = smf;
    float* v   = wfc + 64 * 513;
    float* red = v + 512;
    const int tid = threadIdx.x;

    for (int i = tid; i < 64 * 512; i += 512)
        wfc[(i >> 9) * 513 + (i & 511)] = w1[i];
    __syncthreads();

    const int jj = tid & 63, part = tid >> 6;

    for (int rr = 0; rr < 32; rr++) {
        const int b = blockIdx.x * 32 + rr;
        {
            int c = tid >> 1, p = tid & 1;
            const float* p0 = out2 + ((size_t)b * TT + p * 5) * 256 + c;
            float mx = p0[0];
            mx = fmaxf(mx, p0[256]);  mx = fmaxf(mx, p0[512]);
            mx = fmaxf(mx, p0[768]);  mx = fmaxf(mx, p0[1024]);
            v[tid] = mx;
        }
        __syncthreads();

        float s = 0.0f;
        const float* wr = wfc + jj * 513 + part * 64;
        const float* vr = v + part * 64;
#pragma unroll
        for (int i = 0; i < 64; i++) s += wr[i] * vr[i];
        red[tid] = s;
        __syncthreads();

        if (tid < 64) {
            float h = red[tid]       + red[64 + tid]  + red[128 + tid] +
                      red[192 + tid] + red[256 + tid] + red[320 + tid] +
                      red[384 + tid] + red[448 + tid] + b1[tid];
            h = fmaxf(h, 0.0f);
            red[tid] = h * w2[tid];
        }
        __syncthreads();

        if (tid == 0) {
            float s2 = b2[0];
#pragma unroll
            for (int j2 = 0; j2 < 64; j2++) s2 += red[j2];
            y[b] = s2;
        }
        __syncthreads();
    }
}

// ============================================================================
extern "C" void kernel_launch(void* const* d_in, const int* in_sizes, int n_in,
                              void* d_out, int out_size)
{
    (void)in_sizes; (void)n_in; (void)out_size;
    const float* x     = (const float*)d_in[0];
    const float* wih1f = (const float*)d_in[1];
    const float* whh1f = (const float*)d_in[2];
    const float* bih1f = (const float*)d_in[3];
    const float* bhh1f = (const float*)d_in[4];
    const float* wih1b = (const float*)d_in[5];
    const float* whh1b = (const float*)d_in[6];
    const float* bih1b = (const float*)d_in[7];
    const float* bhh1b = (const float*)d_in[8];
    const float* wih2f = (const float*)d_in[9];
    const float* whh2f = (const float*)d_in[10];
    const float* bih2f = (const float*)d_in[11];
    const float* bhh2f = (const float*)d_in[12];
    const float* wih2b = (const float*)d_in[13];
    const float* whh2b = (const float*)d_in[14];
    const float* bih2b = (const float*)d_in[15];
    const float* bhh2b = (const float*)d_in[16];
    const float* fc1w  = (const float*)d_in[17];
    const float* fc1b  = (const float*)d_in[18];
    const float* fc2w  = (const float*)d_in[19];
    const float* fc2b  = (const float*)d_in[20];
    float* y = (float*)d_out;

    float *xpf, *xpb, *o1, *o2;
    cudaGetSymbolAddress((void**)&xpf, g_xp_f);
    cudaGetSymbolAddress((void**)&xpb, g_xp_b);
    cudaGetSymbolAddress((void**)&o1,  g_out1);
    cudaGetSymbolAddress((void**)&o2,  g_out2);

    cudaFuncSetAttribute(lstm_layer, cudaFuncAttributeMaxDynamicSharedMemorySize,
                         (int)L_SMEM);

    const dim3 xgrid(4, BT / 128);     // xproj: nt fastest -> A-tile L2 reuse
    const dim3 lgrid(2 * (BN / 64), 2);// lstm: (2 cluster CTAs x 256 blks) x 2 dir

    // ---- layer 1 ----
    xproj_mma<<<xgrid, 256, XP_SMEM>>>(x, wih1f, bih1f, bhh1f, xpf, II);
    xproj_mma<<<xgrid, 256, XP_SMEM>>>(x, wih1b, bih1b, bhh1b, xpb, II);
    lstm_layer<<<lgrid, 512, L_SMEM>>>(whh1f, whh1b, xpf, xpb, o1);

    // ---- layer 2 ----
    xproj_mma<<<xgrid, 256, XP_SMEM>>>(o1, wih2f, bih2f, bhh2f, xpf, 256);
    xproj_mma<<<xgrid, 256, XP_SMEM>>>(o1, wih2b, bih2b, bhh2b, xpb, 256);
    lstm_layer<<<lgrid, 512, L_SMEM>>>(whh2f, whh2b, xpf, xpb, o2);

    // ---- pool + FC head ----
    cudaFuncSetAttribute(fc_head, cudaFuncAttributeMaxDynamicSharedMemorySize,
                         (64 * 513 + 512 + 512) * (int)sizeof(float));
    fc_head<<<BN / 32, 512, (64 * 513 + 512 + 512) * sizeof(float)>>>(
        o2, fc1w, fc1b, fc2w, fc2b, y);
}

// round 11
// speedup vs baseline: 2.6694x; 1.1889x over previous
#include <cuda_runtime.h>
#include <cstdint>
#include <cstddef>

#define BN   16384          // batch
#define TT   10             // timesteps
#define II   184            // input features
#define HH   128            // hidden
#define G4   512            // 4*H (gate width)
#define BT   (BN * TT)      // 163840 rows
#define KP1  192            // padded K for layer-1 xproj

// ---------------- scratch (device globals; allocation-free) ----------------
__device__ float g_xp_f[(size_t)BT * G4];
__device__ float g_xp_b[(size_t)BT * G4];
__device__ float g_out1[(size_t)BT * 256];
__device__ float g_out2[(size_t)BT * 256];
__device__ float g_xr[(size_t)BT * KP1];     // tf32-rounded, padded x
__device__ float g_wr[4][512 * 256];         // rounded, padded w_ih (f,b,f2,b2)

// ---------------- helpers ----------------
__device__ __forceinline__ float sigm(float x) {
    return 1.0f / (1.0f + __expf(-x));
}
__device__ __forceinline__ float tf32r(float x) {
    uint32_t r;
    asm("cvt.rna.tf32.f32 %0, %1;" : "=r"(r) : "f"(x));
    return __uint_as_float(r);
}
__device__ __forceinline__ void mma8(float c[4], const uint32_t a[4],
                                     const uint32_t b[2]) {
    asm volatile(
        "mma.sync.aligned.m16n8k8.row.col.f32.tf32.tf32.f32 "
        "{%0,%1,%2,%3}, {%4,%5,%6,%7}, {%8,%9}, {%0,%1,%2,%3};"
        : "+f"(c[0]), "+f"(c[1]), "+f"(c[2]), "+f"(c[3])
        : "r"(a[0]), "r"(a[1]), "r"(a[2]), "r"(a[3]), "r"(b[0]), "r"(b[1]));
}
#define FU __float_as_uint

__device__ __forceinline__ uint32_t smem_u32(const void* p) {
    uint32_t a;
    asm("{ .reg .u64 t; cvta.to.shared.u64 t, %1; cvt.u32.u64 %0, t; }"
        : "=r"(a) : "l"(p));
    return a;
}
__device__ __forceinline__ void st_peer(uint32_t local_addr, uint32_t peer_rank,
                                        float v) {
    uint32_t pa;
    asm volatile("mapa.shared::cluster.u32 %0, %1, %2;"
                 : "=r"(pa) : "r"(local_addr), "r"(peer_rank));
    asm volatile("st.shared::cluster.f32 [%0], %1;" :: "r"(pa), "f"(v)
                 : "memory");
}

// ============================================================================
// Pre-round pass: dst[row][0..KP) = tf32_rna(src[row][0..K)), zero-padded.
// K and KP multiples of 4.
// ============================================================================
__global__ void round_pad(const float* __restrict__ src, float* __restrict__ dst,
                          int K, int KPp, long long total4)
{
    const long long i4 = (long long)blockIdx.x * blockDim.x + threadIdx.x;
    if (i4 >= total4) return;
    const int kp4 = KPp >> 2;
    const long long row = i4 / kp4;
    const int c = (int)(i4 % kp4) * 4;
    float4 v = make_float4(0.f, 0.f, 0.f, 0.f);
    if (c < K) v = *(const float4*)(src + row * K + c);
    float4 o = make_float4(tf32r(v.x), tf32r(v.y), tf32r(v.z), tf32r(v.w));
    *(float4*)(dst + row * KPp + c) = o;
}

// ============================================================================
// xproj GEMM v3: C[M,512] = A[M,KP] @ W[512,KP]^T + (bih + bhh)
// A and W are PRE-ROUNDED tf32 (padded to KP, multiple of 16).
// CTA 128x128, 4 warps (2m x 2n) of 64x64. K chunked by 16, 3-stage cp.async
// pipeline (16B, no cvt/STS), ldmatrix.x4 fragments from 80B-stride rows
// (bank-quad 5r mod 16 -> conflict-free). Grid (nt, mt) for A-tile L2 reuse.
// ============================================================================
#define XST      20480                 // stage bytes: A 128*80 + B 128*80
#define XP_SMEM  (3 * XST)             // 61440

__global__ __launch_bounds__(128, 2)
void xproj_mma(const float* __restrict__ A, const float* __restrict__ W,
               const float* __restrict__ bih, const float* __restrict__ bhh,
               float* __restrict__ C, int KPp)
{
    extern __shared__ char sx[];
    const uint32_t smb = smem_u32(sx);
    const int tid = threadIdx.x, l = tid & 31, w = tid >> 5;
    const int gid = l >> 2, tig = l & 3;
    const int nt = blockIdx.x, mt = blockIdx.y;
    const int warpm = w >> 1, warpn = w & 1;
    const int nblk = KPp >> 4;

    const float* Ag = A + (size_t)mt * 128 * KPp;
    const float* Wg = W + (size_t)nt * 128 * KPp;

    // cp.async mapping: 512 16B-groups per operand, 4 per thread
    const int ckg = tid & 3, crw = tid >> 2;

    auto issue = [&](int c) {
        const uint32_t sA = smb + (c % 3) * XST;
        const uint32_t sB = sA + 10240;
        const float* ga = Ag + c * 16 + ckg * 4;
        const float* gb = Wg + c * 16 + ckg * 4;
#pragma unroll
        for (int i = 0; i < 4; i++) {
            const int r = crw + i * 32;
            asm volatile("cp.async.cg.shared.global [%0], [%1], 16;"
                         :: "r"(sA + r * 80 + ckg * 16),
                            "l"(ga + (size_t)r * KPp) : "memory");
            asm volatile("cp.async.cg.shared.global [%0], [%1], 16;"
                         :: "r"(sB + r * 80 + ckg * 16),
                            "l"(gb + (size_t)r * KPp) : "memory");
        }
    };

    // ldmatrix per-lane offsets (j = lane>>3 selects matrix, i = lane&7 row)
    const int lj = l >> 3, li = l & 7;
    // A x4: matrices (m 0-7,k0-3),(m 8-15,k0-3),(m 0-7,k4-7),(m 8-15,k4-7)
    const uint32_t offA = (uint32_t)((warpm * 64 + (lj & 1) * 8 + li) * 80
                                     + (lj >> 1) * 16);
    // B x4: matrices (n 0-7,k0-3),(n 0-7,k4-7),(n 8-15,k0-3),(n 8-15,k4-7)
    const uint32_t offB = (uint32_t)(10240 + (warpn * 64 + (lj >> 1) * 8 + li) * 80
                                     + (lj & 1) * 16);

    float acc[4][8][4];
#pragma unroll
    for (int m2 = 0; m2 < 4; m2++)
#pragma unroll
        for (int nn = 0; nn < 8; nn++)
#pragma unroll
            for (int r = 0; r < 4; r++) acc[m2][nn][r] = 0.0f;

    issue(0); asm volatile("cp.async.commit_group;" ::: "memory");
    issue(1); asm volatile("cp.async.commit_group;" ::: "memory");
    issue(2); asm volatile("cp.async.commit_group;" ::: "memory");

    for (int c = 0; c < nblk; c++) {
        asm volatile("cp.async.wait_group 2;" ::: "memory");
        __syncthreads();
        const uint32_t stg = smb + (c % 3) * XST;
#pragma unroll
        for (int kk = 0; kk < 2; kk++) {
            uint32_t a[4][4], b[4][4];
#pragma unroll
            for (int m2 = 0; m2 < 4; m2++)
                asm volatile(
                    "ldmatrix.sync.aligned.m8n8.x4.shared.b16 {%0,%1,%2,%3}, [%4];"
                    : "=r"(a[m2][0]), "=r"(a[m2][1]),
                      "=r"(a[m2][2]), "=r"(a[m2][3])
                    : "r"(stg + offA + m2 * 1280 + kk * 32));
#pragma unroll
            for (int n2 = 0; n2 < 4; n2++)
                asm volatile(
                    "ldmatrix.sync.aligned.m8n8.x4.shared.b16 {%0,%1,%2,%3}, [%4];"
                    : "=r"(b[n2][0]), "=r"(b[n2][1]),
                      "=r"(b[n2][2]), "=r"(b[n2][3])
                    : "r"(stg + offB + n2 * 1280 + kk * 32));
#pragma unroll
            for (int m2 = 0; m2 < 4; m2++)
#pragma unroll
                for (int n2 = 0; n2 < 4; n2++) {
                    mma8(acc[m2][n2 * 2],     a[m2], &b[n2][0]);
                    mma8(acc[m2][n2 * 2 + 1], a[m2], &b[n2][2]);
                }
        }
        __syncthreads();
        if (c + 3 < nblk) issue(c + 3);
        asm volatile("cp.async.commit_group;" ::: "memory");  // empty ok
    }

    // epilogue: + bias, write C
#pragma unroll
    for (int m2 = 0; m2 < 4; m2++) {
        const int row = mt * 128 + warpm * 64 + m2 * 16 + gid;
#pragma unroll
        for (int nn = 0; nn < 8; nn++) {
            const int col = nt * 128 + warpn * 64 + nn * 8 + tig * 2;
            const float b0 = bih[col] + bhh[col];
            const float b1 = bih[col + 1] + bhh[col + 1];
            *(float2*)(C + (size_t)row * G4 + col) =
                make_float2(acc[m2][nn][0] + b0, acc[m2][nn][1] + b1);
            *(float2*)(C + (size_t)(row + 8) * G4 + col) =
                make_float2(acc[m2][nn][2] + b0, acc[m2][nn][3] + b1);
        }
    }
}

// ============================================================================
// Persistent LSTM layer kernel (cluster-2, resident Whh slice, h in smem,
// c in registers). Unchanged from R10 except round_out: when set, h written
// to outbuf is tf32-rounded (feeds layer-2 xproj which needs rounded A).
// ============================================================================
#define A_F2S  68                              // A row stride in float2
#define B_F2S  68                              // B row stride in float2
#define A_FLOATS (64 * A_F2S * 2)              // 8704
#define B_FLOATS (256 * B_F2S * 2)             // 34816
#define L_SMEM  ((A_FLOATS + B_FLOATS) * 4)    // 174080 bytes

__global__ __launch_bounds__(512, 1) __cluster_dims__(2, 1, 1)
void lstm_layer(const float* __restrict__ whh_f, const float* __restrict__ whh_b,
                const float* __restrict__ xpf, const float* __restrict__ xpb,
                float* __restrict__ outbuf, int round_out)
{
    extern __shared__ float sl[];
    float*  Afl = sl;
    float2* A2  = (float2*)sl;
    float*  Bfl = sl + A_FLOATS;
    float2* B2  = (float2*)Bfl;

    uint32_t q;
    asm("mov.u32 %0, %%cluster_ctarank;" : "=r"(q));
    const uint32_t peer = q ^ 1u;
    const int rowblk = blockIdx.x >> 1;
    const int dir = blockIdx.y;
    const int row0 = rowblk * 64;
    const float* xp  = dir ? xpb : xpf;
    const float* whh = dir ? whh_b : whh_f;

    const int tid = threadIdx.x, l = tid & 31, w = tid >> 5;
    const int gid = l >> 2, tig = l & 3;
    const int warpm = w >> 3;            // 0..1  (32 rows each)
    const int warpj = w & 7;             // 0..7  (8 j-cols each)

    // ---- load resident Whh slice once: rows n_g = g*128 + q*64 + jl ----
    {
        const int nb = tid >> 1;                 // 0..255 local row
        const int g = nb >> 6, jl = nb & 63;
        const int kh = (tid & 1) * 64;
        const float* src = whh + (size_t)(g * 128 + (int)q * 64 + jl) * HH + kh;
#pragma unroll
        for (int i = 0; i < 16; i++) {
            float4 v = *(const float4*)(src + i * 4);
            const float vv[4] = {tf32r(v.x), tf32r(v.y), tf32r(v.z), tf32r(v.w)};
#pragma unroll
            for (int j = 0; j < 4; j++) {
                const int k = kh + i * 4 + j;
                const int p = (k >> 3) * 4 + (k & 3);
                const int s = (k >> 2) & 1;
                Bfl[nb * (B_F2S * 2) + p * 2 + s] = vv[j];
            }
        }
    }

    // per-thread fixed coordinates
    const int jl2 = warpj * 8 + tig * 2;          // local j of cols (jl2, jl2+1)
    const int jg  = (int)q * 64 + jl2;            // global hidden col
    const int pA  = (jg >> 3) * 4 + (jg & 3);     // A pair index for h writes
    const int sA  = (jg >> 2) & 1;                // slot (same for jg and jg+1)

    float2 cc[4];                                 // cell state (4 rows x 2 cols)

    for (int ti = 0; ti < TT; ti++) {
        const int t = dir ? (TT - 1 - ti) : ti;

        float acc[2][4][4];
#pragma unroll
        for (int m2 = 0; m2 < 2; m2++)
#pragma unroll
            for (int g = 0; g < 4; g++)
#pragma unroll
                for (int r = 0; r < 4; r++) acc[m2][g][r] = 0.0f;

        // prefetch xp for this step (overlaps MMA loop via scoreboard)
        float2 xr[4][4];
#pragma unroll
        for (int r = 0; r < 4; r++) {
            const int brow = row0 + warpm * 32 + (r >> 1) * 16 + (r & 1) * 8 + gid;
            const float* xpr = xp + ((size_t)brow * TT + t) * G4 + jg;
#pragma unroll
            for (int g = 0; g < 4; g++)
                xr[r][g] = *(const float2*)(xpr + g * HH);
        }

        if (ti > 0) {
            const int r0 = warpm * 32 + gid;
#pragma unroll
            for (int kk = 0; kk < 16; kk++) {
                const int p = kk * 4 + tig;
                float2 fa0 = A2[(r0)      * A_F2S + p];
                float2 fa1 = A2[(r0 + 8)  * A_F2S + p];
                float2 fa2 = A2[(r0 + 16) * A_F2S + p];
                float2 fa3 = A2[(r0 + 24) * A_F2S + p];
                const uint32_t a0[4] = {FU(fa0.x), FU(fa1.x), FU(fa0.y), FU(fa1.y)};
                const uint32_t a1[4] = {FU(fa2.x), FU(fa3.x), FU(fa2.y), FU(fa3.y)};
#pragma unroll
                for (int g = 0; g < 4; g++) {
                    const int nb = g * 64 + warpj * 8 + gid;
                    float2 fw = B2[nb * B_F2S + p];
                    const uint32_t bf[2] = {FU(fw.x), FU(fw.y)};
                    mma8(acc[0][g], a0, bf);
                    mma8(acc[1][g], a1, bf);
                }
            }
        }
        __syncthreads();          // all A reads done before cell overwrites A

        // ---- fused LSTM cell; write h to outbuf + both CTAs' A planes ----
#pragma unroll
        for (int r = 0; r < 4; r++) {
            const int m2 = r >> 1, rh = r & 1;
            const int lr = warpm * 32 + m2 * 16 + rh * 8 + gid;
            const int brow = row0 + lr;
            const int e = rh * 2;

            float i0 = sigm(acc[m2][0][e]     + xr[r][0].x);
            float i1 = sigm(acc[m2][0][e + 1] + xr[r][0].y);
            float f0 = sigm(acc[m2][1][e]     + xr[r][1].x);
            float f1 = sigm(acc[m2][1][e + 1] + xr[r][1].y);
            float g0 = tanhf(acc[m2][2][e]     + xr[r][2].x);
            float g1 = tanhf(acc[m2][2][e + 1] + xr[r][2].y);
            float o0 = sigm(acc[m2][3][e]     + xr[r][3].x);
            float o1 = sigm(acc[m2][3][e + 1] + xr[r][3].y);

            float2 cp = (ti > 0) ? cc[r] : make_float2(0.f, 0.f);
            float2 cn = make_float2(f0 * cp.x + i0 * g0, f1 * cp.y + i1 * g1);
            float2 hn = make_float2(o0 * tanhf(cn.x), o1 * tanhf(cn.y));
            cc[r] = cn;

            const float h0 = tf32r(hn.x), h1 = tf32r(hn.y);
            const float2 hw = round_out ? make_float2(h0, h1) : hn;
            *(float2*)(outbuf + ((size_t)brow * TT + t) * 256 + dir * HH + jg) = hw;

            float* dst = &Afl[lr * (A_F2S * 2) + pA * 2 + sA];
            dst[0] = h0;
            dst[2] = h1;                         // pA+1, same slot
            const uint32_t da = smem_u32(dst);
            st_peer(da,     peer, h0);
            st_peer(da + 8, peer, h1);
        }
        __syncthreads();
        asm volatile("barrier.cluster.arrive.aligned;" ::: "memory");
        asm volatile("barrier.cluster.wait.aligned;"   ::: "memory");
    }
}

// ============================================================================
// Max-pool + fc1(relu) + fc2, fused. (unchanged, proven)
// ============================================================================
__global__ void fc_head(const float* __restrict__ out2,
                        const float* __restrict__ w1, const float* __restrict__ b1,
                        const float* __restrict__ w2, const float* __restrict__ b2,
                        float* __restrict__ y)
{
    extern __shared__ float smf[];
    float* wfc = smf;
    float* v   = wfc + 64 * 513;
    float* red = v + 512;
    const int tid = threadIdx.x;

    for (int i = tid; i < 64 * 512; i += 512)
        wfc[(i >> 9) * 513 + (i & 511)] = w1[i];
    __syncthreads();

    const int jj = tid & 63, part = tid >> 6;

    for (int rr = 0; rr < 32; rr++) {
        const int b = blockIdx.x * 32 + rr;
        {
            int c = tid >> 1, p = tid & 1;
            const float* p0 = out2 + ((size_t)b * TT + p * 5) * 256 + c;
            float mx = p0[0];
            mx = fmaxf(mx, p0[256]);  mx = fmaxf(mx, p0[512]);
            mx = fmaxf(mx, p0[768]);  mx = fmaxf(mx, p0[1024]);
            v[tid] = mx;
        }
        __syncthreads();

        float s = 0.0f;
        const float* wr = wfc + jj * 513 + part * 64;
        const float* vr = v + part * 64;
#pragma unroll
        for (int i = 0; i < 64; i++) s += wr[i] * vr[i];
        red[tid] = s;
        __syncthreads();

        if (tid < 64) {
            float h = red[tid]       + red[64 + tid]  + red[128 + tid] +
                      red[192 + tid] + red[256 + tid] + red[320 + tid] +
                      red[384 + tid] + red[448 + tid] + b1[tid];
            h = fmaxf(h, 0.0f);
            red[tid] = h * w2[tid];
        }
        __syncthreads();

        if (tid == 0) {
            float s2 = b2[0];
#pragma unroll
            for (int j2 = 0; j2 < 64; j2++) s2 += red[j2];
            y[b] = s2;
        }
        __syncthreads();
    }
}

// ============================================================================
extern "C" void kernel_launch(void* const* d_in, const int* in_sizes, int n_in,
                              void* d_out, int out_size)
{
    (void)in_sizes; (void)n_in; (void)out_size;
    const float* x     = (const float*)d_in[0];
    const float* wih1f = (const float*)d_in[1];
    const float* whh1f = (const float*)d_in[2];
    const float* bih1f = (const float*)d_in[3];
    const float* bhh1f = (const float*)d_in[4];
    const float* wih1b = (const float*)d_in[5];
    const float* whh1b = (const float*)d_in[6];
    const float* bih1b = (const float*)d_in[7];
    const float* bhh1b = (const float*)d_in[8];
    const float* wih2f = (const float*)d_in[9];
    const float* whh2f = (const float*)d_in[10];
    const float* bih2f = (const float*)d_in[11];
    const float* bhh2f = (const float*)d_in[12];
    const float* wih2b = (const float*)d_in[13];
    const float* whh2b = (const float*)d_in[14];
    const float* bih2b = (const float*)d_in[15];
    const float* bhh2b = (const float*)d_in[16];
    const float* fc1w  = (const float*)d_in[17];
    const float* fc1b  = (const float*)d_in[18];
    const float* fc2w  = (const float*)d_in[19];
    const float* fc2b  = (const float*)d_in[20];
    float* y = (float*)d_out;

    float *xpf, *xpb, *o1, *o2, *xr, *wrb;
    cudaGetSymbolAddress((void**)&xpf, g_xp_f);
    cudaGetSymbolAddress((void**)&xpb, g_xp_b);
    cudaGetSymbolAddress((void**)&o1,  g_out1);
    cudaGetSymbolAddress((void**)&o2,  g_out2);
    cudaGetSymbolAddress((void**)&xr,  g_xr);
    cudaGetSymbolAddress((void**)&wrb, g_wr);
    float* wr1f = wrb + 0 * 512 * 256;
    float* wr1b = wrb + 1 * 512 * 256;
    float* wr2f = wrb + 2 * 512 * 256;
    float* wr2b = wrb + 3 * 512 * 256;

    cudaFuncSetAttribute(xproj_mma, cudaFuncAttributeMaxDynamicSharedMemorySize,
                         (int)XP_SMEM);
    cudaFuncSetAttribute(lstm_layer, cudaFuncAttributeMaxDynamicSharedMemorySize,
                         (int)L_SMEM);

    const dim3 xgrid(4, BT / 128);       // nt fastest -> A-tile L2 reuse
    const dim3 lgrid(2 * (BN / 64), 2);  // (2 cluster CTAs x 256 blks) x 2 dir

    // ---- pre-round passes ----
    const long long t4x = (long long)BT * (KP1 / 4);
    round_pad<<<(unsigned)((t4x + 255) / 256), 256>>>(x, xr, II, KP1, t4x);
    round_pad<<<(512 * 48 + 255) / 256, 256>>>(wih1f, wr1f, II, KP1, 512 * 48);
    round_pad<<<(512 * 48 + 255) / 256, 256>>>(wih1b, wr1b, II, KP1, 512 * 48);
    round_pad<<<(512 * 64 + 255) / 256, 256>>>(wih2f, wr2f, 256, 256, 512 * 64);
    round_pad<<<(512 * 64 + 255) / 256, 256>>>(wih2b, wr2b, 256, 256, 512 * 64);

    // ---- layer 1 ----
    xproj_mma<<<xgrid, 128, XP_SMEM>>>(xr, wr1f, bih1f, bhh1f, xpf, KP1);
    xproj_mma<<<xgrid, 128, XP_SMEM>>>(xr, wr1b, bih1b, bhh1b, xpb, KP1);
    lstm_layer<<<lgrid, 512, L_SMEM>>>(whh1f, whh1b, xpf, xpb, o1, 1);

    // ---- layer 2 (o1 already tf32-rounded at write) ----
    xproj_mma<<<xgrid, 128, XP_SMEM>>>(o1, wr2f, bih2f, bhh2f, xpf, 256);
    xproj_mma<<<xgrid, 128, XP_SMEM>>>(o1, wr2b, bih2b, bhh2b, xpb, 256);
    lstm_layer<<<lgrid, 512, L_SMEM>>>(whh2f, whh2b, xpf, xpb, o2, 0);

    // ---- pool + FC head ----
    cudaFuncSetAttribute(fc_head, cudaFuncAttributeMaxDynamicSharedMemorySize,
                         (64 * 513 + 512 + 512) * (int)sizeof(float));
    fc_head<<<BN / 32, 512, (64 * 513 + 512 + 512) * sizeof(float)>>>(
        o2, fc1w, fc1b, fc2w, fc2b, y);
}